// round 6
// baseline (speedup 1.0000x reference)
#include <cuda_runtime.h>
#include <stdint.h>

#define NN      100000
#define F       128
#define KNBR    64
#define SCAP    80
#define EMAX    3300000

// ---------------- static scratch (no allocations allowed) ----------------
__device__ int   g_idxS[NN];          // node -> S slot (-1 none)
__device__ int   g_idxT[NN];          // node -> T slot (-1 none)
__device__ int   g_sNodes[SCAP];
__device__ int   g_tNodes[NN];
__device__ int   g_sCount;
__device__ int   g_tCount;
__device__ int   g_e2Count;
__device__ int   g_edge64;            // 1 if edge_index is int64
__device__ int   g_nbr64;             // 1 if neighbor_indices is int64
__device__ int   g_e2src[EMAX];       // layer-2 edges (dst in S): src node id
__device__ int   g_e2dst[EMAX];       // layer-2 edges: dst S-slot
__device__ float g_agg1[(size_t)NN * F];   // layer-1 sums per T slot
__device__ int   g_cnt1[NN];
__device__ float g_h[(size_t)NN * F];      // h per T slot
__device__ float g_agg2[SCAP * F];
__device__ int   g_cnt2[SCAP];
__device__ float g_emb[SCAP * F];

// robust scalar index read: works for int32/int64 (LE low word) and float32
__device__ __forceinline__ int read_scalar_idx(const void* p) {
    int v = *(const int*)p;
    if (v >= 0 && v < NN) return v;
    float f = *(const float*)p;
    return (int)f;
}

__device__ __forceinline__ void claimT(int node) {
    int prev = atomicCAS(&g_idxT[node], -1, -2);
    if (prev == -1) {
        int ts = atomicAdd(&g_tCount, 1);
        g_tNodes[ts] = node;
        g_idxT[node] = ts;   // finalized before next kernel reads it
    }
}

// ---------------- kernel 0: init + dtype probes ----------------
__global__ void k_init(const void* edges, const void* nbrs, long long E) {
    int stride = gridDim.x * blockDim.x;
    for (int n = blockIdx.x * blockDim.x + threadIdx.x; n < NN; n += stride) {
        g_idxS[n] = -1;
        g_idxT[n] = -1;
    }
    if (blockIdx.x == 0 && threadIdx.x == 0) {
        g_sCount = 0; g_tCount = 0; g_e2Count = 0;
        // probe edge dtype: int64 interpretation must give values in [0,NN)
        int ok = 1;
        const long long* e64 = (const long long*)edges;
        long long lim = 2 * E < 16 ? 2 * E : 16;
        for (long long t = 0; t < lim; t++) {
            long long v = e64[t];
            if (v < 0 || v >= NN) { ok = 0; break; }
        }
        g_edge64 = ok;
        ok = 1;
        const long long* n64 = (const long long*)nbrs;
        for (int t = 0; t < 16; t++) {
            long long v = n64[t];
            if (v < 0 || v >= NN) { ok = 0; break; }
        }
        g_nbr64 = ok;
    }
}

// ---------------- kernel 1: build S, seed T, zero small accum ----------------
__global__ void k_buildS(const void* nbrs, const void* curr_p, const void* dest_p) {
    int tid = threadIdx.x;
    for (int i = tid; i < SCAP * F; i += blockDim.x) g_agg2[i] = 0.0f;
    for (int i = tid; i < SCAP; i += blockDim.x) g_cnt2[i] = 0;
    if (tid < KNBR + 2) {
        int node;
        if (tid == 0)      node = read_scalar_idx(curr_p);
        else if (tid == 1) node = read_scalar_idx(dest_p);
        else {
            node = g_nbr64 ? (int)((const long long*)nbrs)[tid - 2]
                           : ((const int*)nbrs)[tid - 2];
        }
        if (node >= 0 && node < NN) {
            int prev = atomicCAS(&g_idxS[node], -1, -2);
            if (prev == -1) {
                int s = atomicAdd(&g_sCount, 1);
                g_sNodes[s] = node;
                g_idxS[node] = s;
            }
            claimT(node);
        }
    }
}

// ---------------- kernel 2: scan edges for dst in S ----------------
__global__ void k_scan1(const void* edges, long long E) {
    long long e = (long long)blockIdx.x * blockDim.x + threadIdx.x;
    if (e >= E) return;
    int is64 = g_edge64;
    int d = is64 ? (int)((const long long*)edges)[E + e]
                 : ((const int*)edges)[E + e];
    if ((unsigned)d >= NN) return;
    int ss = g_idxS[d];
    if (ss >= 0) {
        int s = is64 ? (int)((const long long*)edges)[e]
                     : ((const int*)edges)[e];
        if ((unsigned)s >= NN) return;
        atomicAdd(&g_cnt2[ss], 1);
        int pos = atomicAdd(&g_e2Count, 1);
        if (pos < EMAX) { g_e2src[pos] = s; g_e2dst[pos] = ss; }
        claimT(s);
    }
}

// ---------------- kernel 3: zero agg1/cnt1 for the tCount slots ----------------
__global__ void k_zero1() {
    int tc = g_tCount;
    long long tot = (long long)tc * F;
    long long stride = (long long)gridDim.x * blockDim.x;
    for (long long i = (long long)blockIdx.x * blockDim.x + threadIdx.x; i < tot; i += stride)
        g_agg1[i] = 0.0f;
    for (int i = blockIdx.x * blockDim.x + threadIdx.x; i < tc; i += (int)stride)
        g_cnt1[i] = 0;
}

// ---------------- kernel 4: scan edges for dst in T, warp-coop accumulate x[src] ----------------
__global__ void k_scan2(const void* edges, const float* __restrict__ x, long long E) {
    long long e = (long long)blockIdx.x * blockDim.x + threadIdx.x;
    int lane = threadIdx.x & 31;
    int is64 = g_edge64;
    int s = 0, ts = -1;
    bool act = false;
    if (e < E) {
        int d = is64 ? (int)((const long long*)edges)[E + e]
                     : ((const int*)edges)[E + e];
        if ((unsigned)d < NN) {
            ts = g_idxT[d];
            if (ts >= 0) {
                s = is64 ? (int)((const long long*)edges)[e]
                         : ((const int*)edges)[e];
                if ((unsigned)s < NN) {
                    atomicAdd(&g_cnt1[ts], 1);
                    act = true;
                }
            }
        }
    }
    unsigned m = __ballot_sync(0xffffffffu, act);
    while (m) {
        int l = __ffs(m) - 1;
        m &= m - 1;
        int ls = __shfl_sync(0xffffffffu, s, l);
        int lt = __shfl_sync(0xffffffffu, ts, l);
        float4 v = ((const float4*)(x + (size_t)ls * F))[lane];
        float* dp = &g_agg1[(size_t)lt * F + lane * 4];
        asm volatile("red.global.add.v4.f32 [%0], {%1,%2,%3,%4};"
                     :: "l"(dp), "f"(v.x), "f"(v.y), "f"(v.z), "f"(v.w) : "memory");
    }
}

// ---------------- kernel 5: h = relu(mean1 @ W1l + b1 + x @ W1r) at T slots ----------------
__global__ void k_h(const float* __restrict__ x,
                    const float* __restrict__ Wl, const float* __restrict__ Wr,
                    const float* __restrict__ b) {
    __shared__ float sm[8 * F];     // 4 nodes x (mean, x)
    int tc = g_tCount;
    int j = threadIdx.x;            // output feature 0..127
    for (int g0 = blockIdx.x * 4; g0 < tc; g0 += gridDim.x * 4) {
        int nvalid = min(4, tc - g0);
        for (int q = 0; q < nvalid; q++) {
            int t = g0 + q;
            int node = g_tNodes[t];
            float c = (float)max(g_cnt1[t], 1);
            sm[(2 * q + 0) * F + j] = g_agg1[(size_t)t * F + j] / c;
            sm[(2 * q + 1) * F + j] = x[(size_t)node * F + j];
        }
        __syncthreads();
        float acc0 = 0.f, acc1 = 0.f, acc2 = 0.f, acc3 = 0.f;
        #pragma unroll 4
        for (int k = 0; k < F; k++) {
            float wl = Wl[k * F + j];
            float wr = Wr[k * F + j];
            acc0 += sm[0 * F + k] * wl + sm[1 * F + k] * wr;
            acc1 += sm[2 * F + k] * wl + sm[3 * F + k] * wr;
            acc2 += sm[4 * F + k] * wl + sm[5 * F + k] * wr;
            acc3 += sm[6 * F + k] * wl + sm[7 * F + k] * wr;
        }
        float bb = b[j];
        float acc[4] = {acc0, acc1, acc2, acc3};
        for (int q = 0; q < nvalid; q++)
            g_h[(size_t)(g0 + q) * F + j] = fmaxf(acc[q] + bb, 0.0f);
        __syncthreads();
    }
}

// ---------------- kernel 6: layer-2 aggregation (warp per recorded edge) ----------------
__global__ void k_agg2() {
    int ec = g_e2Count; if (ec > EMAX) ec = EMAX;
    int lane = threadIdx.x & 31;
    int warp = (blockIdx.x * blockDim.x + threadIdx.x) >> 5;
    int nw = (gridDim.x * blockDim.x) >> 5;
    for (int i = warp; i < ec; i += nw) {
        int s = g_e2src[i];
        int ss = g_e2dst[i];
        int ts = g_idxT[s];
        float4 v = ((const float4*)&g_h[(size_t)ts * F])[lane];
        float* dp = &g_agg2[(size_t)ss * F + lane * 4];
        asm volatile("red.global.add.v4.f32 [%0], {%1,%2,%3,%4};"
                     :: "l"(dp), "f"(v.x), "f"(v.y), "f"(v.z), "f"(v.w) : "memory");
    }
}

// ---------------- kernel 7: emb = mean2 @ W2l + b2 + h @ W2r at S slots ----------------
__global__ void k_emb(const float* __restrict__ Wl, const float* __restrict__ Wr,
                      const float* __restrict__ b) {
    __shared__ float sm[8 * F];
    int sc = g_sCount;
    int j = threadIdx.x;
    for (int g0 = blockIdx.x * 4; g0 < sc; g0 += gridDim.x * 4) {
        int nvalid = min(4, sc - g0);
        for (int q = 0; q < nvalid; q++) {
            int ss = g0 + q;
            int node = g_sNodes[ss];
            int ts = g_idxT[node];
            float c = (float)max(g_cnt2[ss], 1);
            sm[(2 * q + 0) * F + j] = g_agg2[(size_t)ss * F + j] / c;
            sm[(2 * q + 1) * F + j] = g_h[(size_t)ts * F + j];
        }
        __syncthreads();
        float acc0 = 0.f, acc1 = 0.f, acc2 = 0.f, acc3 = 0.f;
        #pragma unroll 4
        for (int k = 0; k < F; k++) {
            float wl = Wl[k * F + j];
            float wr = Wr[k * F + j];
            acc0 += sm[0 * F + k] * wl + sm[1 * F + k] * wr;
            acc1 += sm[2 * F + k] * wl + sm[3 * F + k] * wr;
            acc2 += sm[4 * F + k] * wl + sm[5 * F + k] * wr;
            acc3 += sm[6 * F + k] * wl + sm[7 * F + k] * wr;
        }
        float bb = b[j];
        float acc[4] = {acc0, acc1, acc2, acc3};
        for (int q = 0; q < nvalid; q++)
            g_emb[(size_t)(g0 + q) * F + j] = acc[q] + bb;
        __syncthreads();
    }
}

// ---------------- kernel 8: MLP head (block per neighbor k) ----------------
__global__ void k_head(const void* nbrs, const void* curr_p, const void* dest_p,
                       const float* __restrict__ W1, const float* __restrict__ b1,
                       const float* __restrict__ W2, const float* __restrict__ b2,
                       float* __restrict__ out) {
    __shared__ float cat[3 * F];
    __shared__ float red[F];
    int k = blockIdx.x;
    int j = threadIdx.x;
    int curr = read_scalar_idx(curr_p);
    int dest = read_scalar_idx(dest_p);
    int nb = g_nbr64 ? (int)((const long long*)nbrs)[k] : ((const int*)nbrs)[k];
    int sc = g_idxS[curr], sd = g_idxS[dest], sn = g_idxS[nb];
    cat[j]         = g_emb[(size_t)sc * F + j];
    cat[F + j]     = g_emb[(size_t)sd * F + j];
    cat[2 * F + j] = g_emb[(size_t)sn * F + j];
    __syncthreads();
    float acc = 0.0f;
    #pragma unroll 4
    for (int c = 0; c < 3 * F; c++)
        acc += cat[c] * W1[c * F + j];
    float hid = fmaxf(acc + b1[j], 0.0f);
    red[j] = hid * W2[j];
    __syncthreads();
    for (int st = 64; st > 0; st >>= 1) {
        if (j < st) red[j] += red[j + st];
        __syncthreads();
    }
    if (j == 0) out[k] = red[0] + b2[0];
}

// ---------------- launch ----------------
extern "C" void kernel_launch(void* const* d_in, const int* in_sizes, int n_in,
                              void* d_out, int out_size) {
    const float* x    = (const float*)d_in[0];
    const void*  edges= d_in[1];
    const void*  curr = d_in[2];
    const void*  dest = d_in[3];
    const void*  nbrs = d_in[4];
    const float* W1l  = (const float*)d_in[5];
    const float* W1r  = (const float*)d_in[6];
    const float* b1   = (const float*)d_in[7];
    const float* W2l  = (const float*)d_in[8];
    const float* W2r  = (const float*)d_in[9];
    const float* b2   = (const float*)d_in[10];
    const float* Wl1  = (const float*)d_in[11];
    const float* bl1  = (const float*)d_in[12];
    const float* Wl2  = (const float*)d_in[13];
    const float* bl2  = (const float*)d_in[14];
    float* out = (float*)d_out;

    long long E = (long long)(in_sizes[1] / 2);
    int eb = (int)((E + 255) / 256);

    k_init<<<200, 512>>>(edges, nbrs, E);
    k_buildS<<<1, 256>>>(nbrs, curr, dest);
    k_scan1<<<eb, 256>>>(edges, E);
    k_zero1<<<512, 256>>>();
    k_scan2<<<eb, 256>>>(edges, x, E);
    k_h<<<592, 128>>>(x, W1l, W1r, b1);
    k_agg2<<<64, 256>>>();
    k_emb<<<20, 128>>>(W2l, W2r, b2);
    k_head<<<KNBR, 128>>>(nbrs, curr, dest, Wl1, bl1, Wl2, bl2, out);
}

// round 7
// speedup vs baseline: 1.0518x; 1.0518x over previous
#include <cuda_runtime.h>
#include <stdint.h>

#define NN      100000
#define F       128
#define KNBR    64
#define SCAP    80
#define TCAP    8192
#define EMAX    3300000
#define NWORDS  ((NN + 31) / 32)

// ---------------- static scratch (zero-initialized; no allocations) ----------------
__device__ unsigned g_bitS[NWORDS];       // S membership bitmap (12.5KB, L1-resident)
__device__ unsigned g_bitT[NWORDS];       // T membership bitmap
__device__ int   g_idxS[NN];              // valid only where bitS set
__device__ int   g_idxT[NN];              // valid only where bitT set
__device__ int   g_sNodes[SCAP];
__device__ int   g_tNodes[TCAP];
__device__ int   g_sCount;
__device__ int   g_tCount;
__device__ int   g_e2Count;
__device__ int   g_edge64;
__device__ int   g_nbr64;
__device__ int   g_e2src[EMAX];
__device__ int   g_e2dst[EMAX];
__device__ float g_agg1[(size_t)TCAP * F];   // zeroed by k_prep each call
__device__ int   g_cnt1[TCAP];
__device__ float g_h[(size_t)TCAP * F];
__device__ float g_agg2[SCAP * F];
__device__ int   g_cnt2[SCAP];

__device__ __forceinline__ int read_scalar_idx(const void* p) {
    int v = *(const int*)p;
    if (v >= 0 && v < NN) return v;
    float f = *(const float*)p;
    return (int)f;
}

__device__ __forceinline__ void claimT(int node) {
    unsigned m = 1u << (node & 31);
    unsigned old = atomicOr(&g_bitT[node >> 5], m);
    if (!(old & m)) {
        int ts = atomicAdd(&g_tCount, 1);
        if (ts < TCAP) { g_tNodes[ts] = node; g_idxT[node] = ts; }
        else g_idxT[node] = 0;
    }
}

// ---------- kernel 1: zero accumulators/bitmaps/counters + dtype probes ----------
__global__ void k_prep(const void* edges, const void* nbrs, long long E) {
    int tid = blockIdx.x * blockDim.x + threadIdx.x;
    int stride = gridDim.x * blockDim.x;
    long long tot = (long long)TCAP * F;
    for (long long i = tid; i < tot; i += stride) g_agg1[i] = 0.0f;
    for (int i = tid; i < TCAP; i += stride) g_cnt1[i] = 0;
    for (int i = tid; i < SCAP * F; i += stride) g_agg2[i] = 0.0f;
    for (int i = tid; i < NWORDS; i += stride) { g_bitS[i] = 0u; g_bitT[i] = 0u; }
    if (tid < SCAP) g_cnt2[tid] = 0;
    if (tid == 0) {
        g_sCount = 0; g_tCount = 0; g_e2Count = 0;
        const long long* e64 = (const long long*)edges;
        int n = (int)(2 * E < 8 ? 2 * E : 8);
        long long v0 = 0, v1 = 0, v2 = 0, v3 = 0, v4 = 0, v5 = 0, v6 = 0, v7 = 0;
        if (n > 0) v0 = e64[0]; if (n > 1) v1 = e64[1];
        if (n > 2) v2 = e64[2]; if (n > 3) v3 = e64[3];
        if (n > 4) v4 = e64[4]; if (n > 5) v5 = e64[5];
        if (n > 6) v6 = e64[6]; if (n > 7) v7 = e64[7];
        int ok = 1;
        long long vs[8] = {v0, v1, v2, v3, v4, v5, v6, v7};
        for (int t = 0; t < n; t++) if (vs[t] < 0 || vs[t] >= NN) ok = 0;
        g_edge64 = ok;
        const long long* n64 = (const long long*)nbrs;
        long long w0 = n64[0], w1 = n64[1], w2 = n64[2], w3 = n64[3];
        long long w4 = n64[4], w5 = n64[5], w6 = n64[6], w7 = n64[7];
        ok = 1;
        long long ws[8] = {w0, w1, w2, w3, w4, w5, w6, w7};
        for (int t = 0; t < 8; t++) if (ws[t] < 0 || ws[t] >= NN) ok = 0;
        g_nbr64 = ok;
    }
}

// ---------- kernel 2: build S (curr, dest, 64 neighbors), seed T ----------
__global__ void k_buildS(const void* nbrs, const void* curr_p, const void* dest_p) {
    int tid = threadIdx.x;
    if (tid < KNBR + 2) {
        int node;
        if (tid == 0)      node = read_scalar_idx(curr_p);
        else if (tid == 1) node = read_scalar_idx(dest_p);
        else node = g_nbr64 ? (int)((const long long*)nbrs)[tid - 2]
                            : ((const int*)nbrs)[tid - 2];
        if (node >= 0 && node < NN) {
            unsigned m = 1u << (node & 31);
            unsigned old = atomicOr(&g_bitS[node >> 5], m);
            if (!(old & m)) {
                int s = atomicAdd(&g_sCount, 1);
                if (s < SCAP) { g_sNodes[s] = node; g_idxS[node] = s; }
            }
            claimT(node);
        }
    }
}

// ---------- kernel 3: scan edges, dst in S -> record e2 edge, claim src into T ----------
__global__ void k_scan1(const void* __restrict__ edges, long long E) {
    long long e = (long long)blockIdx.x * blockDim.x + threadIdx.x;
    if (e >= E) return;
    int is64 = g_edge64;
    int d = is64 ? (int)__ldg((const long long*)edges + E + e)
                 : __ldg((const int*)edges + E + e);
    if ((unsigned)d >= NN) return;
    if (g_bitS[d >> 5] & (1u << (d & 31))) {
        int ss = g_idxS[d];
        int s = is64 ? (int)__ldg((const long long*)edges + e)
                     : __ldg((const int*)edges + e);
        if ((unsigned)s >= NN) return;
        atomicAdd(&g_cnt2[ss], 1);
        int pos = atomicAdd(&g_e2Count, 1);
        if (pos < EMAX) { g_e2src[pos] = s; g_e2dst[pos] = ss; }
        claimT(s);
    }
}

// ---------- kernel 4: scan edges, dst in T -> warp-coop accumulate x[src] ----------
__global__ void k_scan2(const void* __restrict__ edges, const float* __restrict__ x,
                        long long E) {
    long long e = (long long)blockIdx.x * blockDim.x + threadIdx.x;
    int lane = threadIdx.x & 31;
    int is64 = g_edge64;
    int s = 0, ts = -1;
    bool act = false;
    if (e < E) {
        int d = is64 ? (int)__ldg((const long long*)edges + E + e)
                     : __ldg((const int*)edges + E + e);
        if ((unsigned)d < NN && (g_bitT[d >> 5] & (1u << (d & 31)))) {
            ts = g_idxT[d];
            s = is64 ? (int)__ldg((const long long*)edges + e)
                     : __ldg((const int*)edges + e);
            if ((unsigned)s < NN) {
                atomicAdd(&g_cnt1[ts], 1);
                act = true;
            }
        }
    }
    unsigned m = __ballot_sync(0xffffffffu, act);
    while (m) {
        int l = __ffs(m) - 1;
        m &= m - 1;
        int ls = __shfl_sync(0xffffffffu, s, l);
        int lt = __shfl_sync(0xffffffffu, ts, l);
        float4 v = __ldg((const float4*)(x + (size_t)ls * F) + lane);
        float* dp = &g_agg1[(size_t)lt * F + lane * 4];
        asm volatile("red.global.add.v4.f32 [%0], {%1,%2,%3,%4};"
                     :: "l"(dp), "f"(v.x), "f"(v.y), "f"(v.z), "f"(v.w) : "memory");
    }
}

// ---------- kernel 5: h = relu(mean1 @ W1l + b1 + x @ W1r) at T slots ----------
// 8 nodes/tile; transposed smem layout sm[k*20 + row] (row = 2q:mean, 2q+1:x)
// so the inner loop uses 4x LDS.128 broadcasts per k instead of 16 scalar LDS.
__global__ void k_h(const float* __restrict__ x,
                    const float* __restrict__ Wl, const float* __restrict__ Wr,
                    const float* __restrict__ b) {
    __shared__ float sm[F * 20];
    int tc = g_tCount; if (tc > TCAP) tc = TCAP;
    int j = threadIdx.x;             // output feature / staging feature
    for (int tile = blockIdx.x; tile * 8 < tc; tile += gridDim.x) {
        int g0 = tile * 8;
        int nvalid = min(8, tc - g0);
        #pragma unroll
        for (int q = 0; q < 8; q++) {
            float mv = 0.0f, xv = 0.0f;
            if (q < nvalid) {
                int t = g0 + q;
                int node = g_tNodes[t];
                float inv = 1.0f / (float)max(g_cnt1[t], 1);
                mv = g_agg1[(size_t)t * F + j] * inv;
                xv = x[(size_t)node * F + j];
            }
            sm[j * 20 + 2 * q]     = mv;
            sm[j * 20 + 2 * q + 1] = xv;
        }
        __syncthreads();
        float a0 = 0.f, a1 = 0.f, a2 = 0.f, a3 = 0.f, a4 = 0.f, a5 = 0.f, a6 = 0.f, a7 = 0.f;
        #pragma unroll 4
        for (int k = 0; k < F; k++) {
            const float4* row = (const float4*)&sm[k * 20];
            float4 r0 = row[0], r1 = row[1], r2 = row[2], r3 = row[3];
            float wl = Wl[k * F + j];
            float wr = Wr[k * F + j];
            a0 += r0.x * wl + r0.y * wr;
            a1 += r0.z * wl + r0.w * wr;
            a2 += r1.x * wl + r1.y * wr;
            a3 += r1.z * wl + r1.w * wr;
            a4 += r2.x * wl + r2.y * wr;
            a5 += r2.z * wl + r2.w * wr;
            a6 += r3.x * wl + r3.y * wr;
            a7 += r3.z * wl + r3.w * wr;
        }
        float bb = b[j];
        float acc[8] = {a0, a1, a2, a3, a4, a5, a6, a7};
        for (int q = 0; q < nvalid; q++)
            g_h[(size_t)(g0 + q) * F + j] = fmaxf(acc[q] + bb, 0.0f);
        __syncthreads();
    }
}

// ---------- kernel 6: layer-2 aggregation (warp per recorded edge) ----------
__global__ void k_agg2() {
    int ec = g_e2Count; if (ec > EMAX) ec = EMAX;
    int lane = threadIdx.x & 31;
    int warp = (blockIdx.x * blockDim.x + threadIdx.x) >> 5;
    int nw = (gridDim.x * blockDim.x) >> 5;
    for (int i = warp; i < ec; i += nw) {
        int s = g_e2src[i];
        int ss = g_e2dst[i];
        int ts = g_idxT[s];
        float4 v = ((const float4*)&g_h[(size_t)ts * F])[lane];
        float* dp = &g_agg2[(size_t)ss * F + lane * 4];
        asm volatile("red.global.add.v4.f32 [%0], {%1,%2,%3,%4};"
                     :: "l"(dp), "f"(v.x), "f"(v.y), "f"(v.z), "f"(v.w) : "memory");
    }
}

// ---------- kernel 7: inline emb (layer-2 linear) for 3 nodes + MLP head ----------
__global__ void k_head(const void* nbrs, const void* curr_p, const void* dest_p,
                       const float* __restrict__ W2l, const float* __restrict__ W2r,
                       const float* __restrict__ b2,
                       const float* __restrict__ W1, const float* __restrict__ b1,
                       const float* __restrict__ W2, const float* __restrict__ bo,
                       float* __restrict__ out) {
    __shared__ float rows[6 * F];     // {mean2, h} for curr, dest, nbr
    __shared__ float cat[3 * F];      // emb for the 3 nodes
    __shared__ float red[F];
    int k = blockIdx.x;
    int j = threadIdx.x;
    int nodes[3];
    nodes[0] = read_scalar_idx(curr_p);
    nodes[1] = read_scalar_idx(dest_p);
    nodes[2] = g_nbr64 ? (int)((const long long*)nbrs)[k] : ((const int*)nbrs)[k];
    #pragma unroll
    for (int i = 0; i < 3; i++) {
        int n = nodes[i];
        int ss = g_idxS[n];
        int ts = g_idxT[n];
        float inv = 1.0f / (float)max(g_cnt2[ss], 1);
        rows[(2 * i) * F + j]     = g_agg2[(size_t)ss * F + j] * inv;
        rows[(2 * i + 1) * F + j] = g_h[(size_t)ts * F + j];
    }
    __syncthreads();
    float e0 = 0.f, e1 = 0.f, e2 = 0.f;
    #pragma unroll 4
    for (int kk = 0; kk < F; kk++) {
        float wl = W2l[kk * F + j];
        float wr = W2r[kk * F + j];
        e0 += rows[0 * F + kk] * wl + rows[1 * F + kk] * wr;
        e1 += rows[2 * F + kk] * wl + rows[3 * F + kk] * wr;
        e2 += rows[4 * F + kk] * wl + rows[5 * F + kk] * wr;
    }
    float bb = b2[j];
    cat[j]         = e0 + bb;
    cat[F + j]     = e1 + bb;
    cat[2 * F + j] = e2 + bb;
    __syncthreads();
    float acc = 0.0f;
    #pragma unroll 4
    for (int c = 0; c < 3 * F; c++)
        acc += cat[c] * W1[c * F + j];
    float hid = fmaxf(acc + b1[j], 0.0f);
    red[j] = hid * W2[j];
    __syncthreads();
    for (int st = 64; st > 0; st >>= 1) {
        if (j < st) red[j] += red[j + st];
        __syncthreads();
    }
    if (j == 0) out[k] = red[0] + bo[0];
}

// ---------------- launch ----------------
extern "C" void kernel_launch(void* const* d_in, const int* in_sizes, int n_in,
                              void* d_out, int out_size) {
    const float* x    = (const float*)d_in[0];
    const void*  edges= d_in[1];
    const void*  curr = d_in[2];
    const void*  dest = d_in[3];
    const void*  nbrs = d_in[4];
    const float* W1l  = (const float*)d_in[5];
    const float* W1r  = (const float*)d_in[6];
    const float* b1   = (const float*)d_in[7];
    const float* W2l  = (const float*)d_in[8];
    const float* W2r  = (const float*)d_in[9];
    const float* b2   = (const float*)d_in[10];
    const float* Wl1  = (const float*)d_in[11];
    const float* bl1  = (const float*)d_in[12];
    const float* Wl2  = (const float*)d_in[13];
    const float* bl2  = (const float*)d_in[14];
    float* out = (float*)d_out;

    long long E = (long long)(in_sizes[1] / 2);
    int eb = (int)((E + 255) / 256);

    k_prep<<<256, 256>>>(edges, nbrs, E);
    k_buildS<<<1, 128>>>(nbrs, curr, dest);
    k_scan1<<<eb, 256>>>(edges, E);
    k_scan2<<<eb, 256>>>(edges, x, E);
    k_h<<<296, 128>>>(x, W1l, W1r, b1);
    k_agg2<<<96, 256>>>();
    k_head<<<KNBR, 128>>>(nbrs, curr, dest, W2l, W2r, b2, Wl1, bl1, Wl2, bl2, out);
}